// round 3
// baseline (speedup 1.0000x reference)
#include <cuda_runtime.h>
#include <math.h>

// Problem shape (from setup_inputs): N=100000, E=1600000, F=H1=H2=128, C=40
#define NN 100000
#define EE 1600000

// ---------------- device scratch (no runtime allocation allowed) ----------------
__device__ float g_bufA[(size_t)NN * 128];
__device__ float g_bufB[(size_t)NN * 128];
__device__ float g_h3[(size_t)NN * 64];      // layer-3 GEMM out, padded 40->64
__device__ float g_dinv[NN];
__device__ int   g_rowptr[NN + 1];
__device__ int   g_cursor[NN];               // doubles as degree counts
__device__ int   g_esrc[EE];
__device__ int   g_partials[256];
__device__ int   g_is64;

// ---------------- edge_index dtype detection ----------------
// If data is int64 (values < 2^31), every odd int32 word is 0.
__global__ void k_detect(const int* __restrict__ ei32, int n_check) {
    if (blockIdx.x == 0 && threadIdx.x == 0) {
        int is64 = 1;
        for (int i = 0; i < n_check; i++)
            if (ei32[2 * i + 1] != 0) { is64 = 0; break; }
        g_is64 = is64;
    }
}

__device__ __forceinline__ int load_idx(const void* ei, long long pos) {
    return g_is64 ? (int)((const long long*)ei)[pos] : ((const int*)ei)[pos];
}

// ---------------- CSR construction ----------------
__global__ void k_zero_counts(int N) {
    int i = blockIdx.x * blockDim.x + threadIdx.x;
    if (i < N) g_cursor[i] = 0;
}

__global__ void k_hist(const void* __restrict__ ei, int E, int N) {
    int e = blockIdx.x * blockDim.x + threadIdx.x;
    if (e < E) {
        int d = load_idx(ei, (long long)E + e);
        if ((unsigned)d < (unsigned)N) atomicAdd(&g_cursor[d], 1);
    }
}

__global__ void k_dinv(int N) {
    int i = blockIdx.x * blockDim.x + threadIdx.x;
    if (i < N) g_dinv[i] = rsqrtf((float)(g_cursor[i] + 1));  // +1 self loop
}

template <int NT>
__device__ __forceinline__ int block_exscan(int v) {
    __shared__ int ws[NT / 32];
    int lane = threadIdx.x & 31, wid = threadIdx.x >> 5;
    int x = v;
#pragma unroll
    for (int o = 1; o < 32; o <<= 1) {
        int y = __shfl_up_sync(0xffffffffu, x, o);
        if (lane >= o) x += y;
    }
    if (lane == 31) ws[wid] = x;
    __syncthreads();
    if (wid == 0) {
        int w = (lane < NT / 32) ? ws[lane] : 0;
#pragma unroll
        for (int o = 1; o < 32; o <<= 1) {
            int y = __shfl_up_sync(0xffffffffu, w, o);
            if (lane >= o) w += y;
        }
        if (lane < NT / 32) ws[lane] = w;
    }
    __syncthreads();
    int base = wid ? ws[wid - 1] : 0;
    return base + x - v;  // exclusive
}

__global__ void k_scan1(int N) {
    int gid = blockIdx.x * 512 + threadIdx.x;
    int v = (gid < N) ? g_cursor[gid] : 0;
    int ex = block_exscan<512>(v);
    if (gid < N) g_rowptr[gid] = ex;
    if (threadIdx.x == 511) g_partials[blockIdx.x] = ex + v;
}

__global__ void k_scan2(int NB) {
    int v = (threadIdx.x < NB) ? g_partials[threadIdx.x] : 0;
    int ex = block_exscan<256>(v);
    if (threadIdx.x < NB) g_partials[threadIdx.x] = ex;
}

__global__ void k_scan3(int N, int E) {
    int gid = blockIdx.x * 512 + threadIdx.x;
    if (gid < N) {
        int r = g_rowptr[gid] + g_partials[blockIdx.x];
        g_rowptr[gid] = r;
        g_cursor[gid] = r;  // write cursor for scatter
    }
    if (gid == 0) g_rowptr[N] = E;
}

__global__ void k_scatter(const void* __restrict__ ei, int E, int N) {
    int e = blockIdx.x * blockDim.x + threadIdx.x;
    if (e < E) {
        int s = load_idx(ei, e);
        int d = load_idx(ei, (long long)E + e);
        if ((unsigned)d < (unsigned)N && (unsigned)s < (unsigned)N) {
            int p = atomicAdd(&g_cursor[d], 1);
            if ((unsigned)p < (unsigned)EE) g_esrc[p] = s;
        }
    }
}

// ---------------- GEMM: C[N,BN] = A[N,128] @ W[128,KW] (zero pad to BN) ----------------
// 128x(BN) block tile, 256 threads, 8xTN micro-tile, K chunked by 32, static smem.
template <int BN, int TN>
__global__ __launch_bounds__(256) void k_gemm(const float* __restrict__ A,
                                              const float* __restrict__ W,
                                              float* __restrict__ C, int N, int KW) {
    __shared__ float As[128 * 33];   // [128][33] padded
    __shared__ float Ws[32 * BN];    // [32][BN]
    int tid = threadIdx.x;
    int tx = tid & 15, ty = tid >> 4;
    int m0 = blockIdx.x * 128;

    float acc[8][TN];
#pragma unroll
    for (int i = 0; i < 8; i++)
#pragma unroll
        for (int j = 0; j < TN; j++) acc[i][j] = 0.f;

    for (int kc = 0; kc < 128; kc += 32) {
        // As: 128 rows x 32 k (1024 float4s / 256 threads = 4 each)
#pragma unroll
        for (int t = 0; t < 4; t++) {
            int idx = tid + t * 256;
            int r = idx >> 3;
            int c4 = (idx & 7) * 4;
            float4 v = make_float4(0.f, 0.f, 0.f, 0.f);
            if (m0 + r < N)
                v = *(const float4*)(A + (size_t)(m0 + r) * 128 + kc + c4);
            As[r * 33 + c4 + 0] = v.x;
            As[r * 33 + c4 + 1] = v.y;
            As[r * 33 + c4 + 2] = v.z;
            As[r * 33 + c4 + 3] = v.w;
        }
        // Ws: 32 x BN (scalar, zero-padded beyond KW)
#pragma unroll
        for (int t = 0; t < (32 * BN) / 256; t++) {
            int idx = tid + t * 256;
            int k = idx / BN, c = idx % BN;
            Ws[k * BN + c] = (c < KW) ? W[(size_t)(kc + k) * KW + c] : 0.f;
        }
        __syncthreads();
#pragma unroll 4
        for (int k = 0; k < 32; k++) {
            float a[8];
#pragma unroll
            for (int i = 0; i < 8; i++) a[i] = As[(ty * 8 + i) * 33 + k];
            float w[TN];
#pragma unroll
            for (int j = 0; j < TN; j++) w[j] = Ws[k * BN + tx * TN + j];
#pragma unroll
            for (int i = 0; i < 8; i++)
#pragma unroll
                for (int j = 0; j < TN; j++) acc[i][j] += a[i] * w[j];
        }
        __syncthreads();
    }
#pragma unroll
    for (int i = 0; i < 8; i++) {
        int r = m0 + ty * 8 + i;
        if (r < N) {
            float* cp = C + (size_t)r * BN + tx * TN;
#pragma unroll
            for (int j = 0; j < TN; j += 4)
                *(float4*)(cp + j) =
                    make_float4(acc[i][j], acc[i][j + 1], acc[i][j + 2], acc[i][j + 3]);
        }
    }
}

// ---------------- Aggregation (128 feat): warp per dst node, bias+ReLU fused ----------------
__global__ __launch_bounds__(256) void k_agg128(const float* __restrict__ h,
                                                const float* __restrict__ bias,
                                                float* __restrict__ out, int N,
                                                int do_relu) {
    int node = (blockIdx.x * blockDim.x + threadIdx.x) >> 5;
    if (node >= N) return;
    int lane = threadIdx.x & 31;
    const float4* h4 = (const float4*)h;
    int beg = g_rowptr[node], end = g_rowptr[node + 1];

    float ax = 0, ay = 0, az = 0, aw = 0;
    float bx = 0, by = 0, bz = 0, bw = 0;
    int e = beg;
    for (; e + 2 <= end; e += 2) {
        int s0 = g_esrc[e], s1 = g_esrc[e + 1];
        float w0 = g_dinv[s0], w1 = g_dinv[s1];
        float4 v0 = h4[(size_t)s0 * 32 + lane];
        float4 v1 = h4[(size_t)s1 * 32 + lane];
        ax += w0 * v0.x; ay += w0 * v0.y; az += w0 * v0.z; aw += w0 * v0.w;
        bx += w1 * v1.x; by += w1 * v1.y; bz += w1 * v1.z; bw += w1 * v1.w;
    }
    if (e < end) {
        int s0 = g_esrc[e];
        float w0 = g_dinv[s0];
        float4 v0 = h4[(size_t)s0 * 32 + lane];
        ax += w0 * v0.x; ay += w0 * v0.y; az += w0 * v0.z; aw += w0 * v0.w;
    }
    float dd = g_dinv[node];
    float4 vs = h4[(size_t)node * 32 + lane];
    ax += bx + dd * vs.x;
    ay += by + dd * vs.y;
    az += bz + dd * vs.z;
    aw += bw + dd * vs.w;
    float4 bb = ((const float4*)bias)[lane];
    float4 o;
    o.x = dd * ax + bb.x;
    o.y = dd * ay + bb.y;
    o.z = dd * az + bb.z;
    o.w = dd * aw + bb.w;
    if (do_relu) {
        o.x = fmaxf(o.x, 0.f); o.y = fmaxf(o.y, 0.f);
        o.z = fmaxf(o.z, 0.f); o.w = fmaxf(o.w, 0.f);
    }
    ((float4*)out)[(size_t)node * 32 + lane] = o;
}

// ---------------- Aggregation (40 feat, stride 64) + fused log_softmax ----------------
__global__ __launch_bounds__(256) void k_agg40(const float* __restrict__ h,
                                               const float* __restrict__ bias,
                                               float* __restrict__ out, int N) {
    int node = (blockIdx.x * blockDim.x + threadIdx.x) >> 5;
    if (node >= N) return;
    int lane = threadIdx.x & 31;
    int beg = g_rowptr[node], end = g_rowptr[node + 1];
    float a0 = 0.f, a1 = 0.f;
    for (int e = beg; e < end; e++) {
        int s = g_esrc[e];
        float wv = g_dinv[s];
        const float* hp = h + (size_t)s * 64;
        a0 += wv * hp[lane];
        a1 += wv * hp[32 + lane];  // cols 40..63 are exact zeros
    }
    float dd = g_dinv[node];
    const float* hs = h + (size_t)node * 64;
    a0 += dd * hs[lane];
    a1 += dd * hs[32 + lane];
    float l0 = dd * a0 + bias[lane];
    float l1 = -3.4e38f;
    if (lane < 8) l1 = dd * a1 + bias[32 + lane];
    float m = fmaxf(l0, l1);
#pragma unroll
    for (int o = 16; o; o >>= 1) m = fmaxf(m, __shfl_xor_sync(0xffffffffu, m, o));
    float s = expf(l0 - m) + ((lane < 8) ? expf(l1 - m) : 0.f);
#pragma unroll
    for (int o = 16; o; o >>= 1) s += __shfl_xor_sync(0xffffffffu, s, o);
    float ls = logf(s);
    out[(size_t)node * 40 + lane] = l0 - m - ls;
    if (lane < 8) out[(size_t)node * 40 + 32 + lane] = l1 - m - ls;
}

// ---------------- host launcher ----------------
extern "C" void kernel_launch(void* const* d_in, const int* in_sizes, int n_in,
                              void* d_out, int out_size) {
    const float* x = (const float*)d_in[0];
    const void* ei = d_in[1];
    const float* W1 = (const float*)d_in[2];
    const float* b1 = (const float*)d_in[3];
    const float* W2 = (const float*)d_in[4];
    const float* b2 = (const float*)d_in[5];
    const float* W3 = (const float*)d_in[6];
    const float* b3 = (const float*)d_in[7];

    int N = in_sizes[0] / 128;
    int E = in_sizes[1] / 2;

    int NB = (N + 511) / 512;
    int EB = (E + 255) / 256;
    int GB = (N + 127) / 128;
    int AB = (N + 7) / 8;  // 8 warps (256 threads) per block -> 8 nodes/block

    k_detect<<<1, 32>>>((const int*)ei, 64);
    k_zero_counts<<<NB, 512>>>(N);
    k_hist<<<EB, 256>>>(ei, E, N);
    k_dinv<<<NB, 512>>>(N);
    k_scan1<<<NB, 512>>>(N);
    k_scan2<<<1, 256>>>(NB);
    k_scan3<<<NB, 512>>>(N, E);
    k_scatter<<<EB, 256>>>(ei, E, N);

    // Layer 1
    k_gemm<128, 8><<<GB, 256>>>(x, W1, g_bufA, N, 128);
    k_agg128<<<AB, 256>>>(g_bufA, b1, g_bufB, N, 1);
    // Layer 2
    k_gemm<128, 8><<<GB, 256>>>(g_bufB, W2, g_bufA, N, 128);
    k_agg128<<<AB, 256>>>(g_bufA, b2, g_bufB, N, 1);
    // Layer 3 + log_softmax
    k_gemm<64, 4><<<GB, 256>>>(g_bufB, W3, g_h3, N, 40);
    k_agg40<<<AB, 256>>>(g_h3, b3, (float*)d_out, N);
}